// round 7
// baseline (speedup 1.0000x reference)
#include <cuda_runtime.h>
#include <cuda_bf16.h>
#include <cstdint>

#define N_NODES 40000
#define N_PAD   40064   // 313 * 128
#define N_EDGES 640000
#define HID 128
#define N_LAYERS 4
#define NUM_GRAPHS 256

#define GT 256          // 8 warps per GEMM CTA

// B tile in SMEM: padded row-major [n][k] bf16, 128 rows x 272B; hi at 0, lo at +TILE_BYTES
#define LDB 272
#define TILE_BYTES 34816
#define SMEM_SZ 69632   // hi + lo  -> 2 CTAs/SM

// ---------------------------------------------------------------------------
// Scratch. h and e live ONLY as pre-split bf16 hi/lo, interleaved per col-pair:
//   buf[row*64 + col/2] = { hi_pair(bf16x2), lo_pair(bf16x2) }
// ---------------------------------------------------------------------------
__device__ uint2 g_hbf[2][(size_t)N_PAD * 64];
__device__ uint2 g_ebf[2][(size_t)N_EDGES * 64];
__device__ float g_P[(size_t)N_PAD * 4 * HID];     // [N,512]: hWm_s | hWm_r | hWe_s | hWe_r (fp32)
__device__ float g_agg[(size_t)N_PAD * HID];       // fp32 scatter-add target
// 33 weight slots: each = hi image (34816 B) + lo image (34816 B), padded [n][k]
__device__ uint4 g_Bw[(size_t)33 * 4352];

// ---------------------------------------------------------------------------
// PTX helpers (baseline ISA only)
// ---------------------------------------------------------------------------
__device__ __forceinline__ uint32_t smem_u32(const void* p) {
    uint32_t a;
    asm("{ .reg .u64 t; cvta.to.shared.u64 t, %1; cvt.u32.u64 %0, t; }" : "=r"(a) : "l"(p));
    return a;
}
__device__ __forceinline__ void red_add_v2(float* addr, float a, float b) {
    asm volatile("red.global.add.v2.f32 [%0], {%1, %2};"
                 :: "l"(addr), "f"(a), "f"(b) : "memory");
}
__device__ __forceinline__ void ldsm_x4(uint32_t addr, uint32_t r[4]) {
    asm volatile("ldmatrix.sync.aligned.m8n8.x4.shared.b16 {%0,%1,%2,%3}, [%4];"
                 : "=r"(r[0]), "=r"(r[1]), "=r"(r[2]), "=r"(r[3]) : "r"(addr));
}
__device__ __forceinline__ void mma_bf16(float c[4], const uint32_t a[4], uint32_t b0, uint32_t b1) {
    asm volatile("mma.sync.aligned.m16n8k16.row.col.f32.bf16.bf16.f32 "
                 "{%0,%1,%2,%3}, {%4,%5,%6,%7}, {%8,%9}, {%0,%1,%2,%3};"
                 : "+f"(c[0]), "+f"(c[1]), "+f"(c[2]), "+f"(c[3])
                 : "r"(a[0]), "r"(a[1]), "r"(a[2]), "r"(a[3]), "r"(b0), "r"(b1));
}
__device__ __forceinline__ uint32_t pack_hi_lo(float a, float b, uint32_t& lo_out) {
    __nv_bfloat16 ha = __float2bfloat16_rn(a), hb = __float2bfloat16_rn(b);
    float ra = a - __bfloat162float(ha), rb = b - __bfloat162float(hb);
    __nv_bfloat16 la = __float2bfloat16_rn(ra), lb = __float2bfloat16_rn(rb);
    lo_out = (uint32_t)__bfloat16_as_ushort(la) | ((uint32_t)__bfloat16_as_ushort(lb) << 16);
    return (uint32_t)__bfloat16_as_ushort(ha) | ((uint32_t)__bfloat16_as_ushort(hb) << 16);
}
__device__ __forceinline__ uint2 pack_pair(float x, float y) {
    uint2 o; o.x = pack_hi_lo(x, y, o.y); return o;
}

// Stage B: copy pre-split hi+lo images (69632 B) from g_Bw slot into SMEM
__device__ __forceinline__ void stage_B(int slot, int tid, char* smem)
{
    const uint4* src = g_Bw + (size_t)slot * 4352;
    uint4* dst = (uint4*)smem;
#pragma unroll
    for (int i = 0; i < 17; i++) dst[tid + i * 256] = src[tid + i * 256];
}

// ---------------------------------------------------------------------------
// A loaders. Fragment slot av[mi*4 + jh + 2*jc] covers
//   row = row0 + mi*16 + jh*8 + (lane>>2), colpair = k0/2 + (lane&3) + jc*4
// ---------------------------------------------------------------------------
__device__ __forceinline__ void load_A_bf(const uint2* __restrict__ A, int row0, int k0p,
                                          int lane, uint2 av[8])
{
    const int r = row0 + (lane >> 2);
    const int cp = k0p + (lane & 3);
#pragma unroll
    for (int mi = 0; mi < 2; mi++)
#pragma unroll
        for (int p = 0; p < 4; p++) {
            int row = r + mi * 16 + (p & 1) * 8;
            av[mi * 4 + p] = A[(size_t)row * 64 + cp + (p >> 1) * 4];
        }
}
template<bool GUARD>
__device__ __forceinline__ void load_A_raw(const float* __restrict__ A, int row0, int k0,
                                           int lane, float2 av[8])
{
    const int r = row0 + (lane >> 2);
    const int c = k0 + (lane & 3) * 2;
#pragma unroll
    for (int mi = 0; mi < 2; mi++)
#pragma unroll
        for (int jh = 0; jh < 2; jh++) {
            int row = r + mi * 16 + jh * 8;
            const float* rp = A + (size_t)row * HID + c;
#pragma unroll
            for (int jc = 0; jc < 2; jc++) {
                float2 v = make_float2(0.f, 0.f);
                if (!GUARD || row < N_NODES) v = *(const float2*)(rp + jc * 8);
                av[mi * 4 + jh + 2 * jc] = v;
            }
        }
}

// ---------------------------------------------------------------------------
// 48-MMA inner block shared by both passes
// ---------------------------------------------------------------------------
__device__ __forceinline__ void mma_block(const uint32_t ah[8], const uint32_t al[8],
                                          uint32_t bBase, uint32_t ko, float acc[2][8][4])
{
#pragma unroll
    for (int nb = 0; nb < 4; nb++) {
        uint32_t bh[4], bl[4];
        ldsm_x4(bBase + nb * 16 * LDB + ko, bh);
        ldsm_x4(bBase + nb * 16 * LDB + ko + TILE_BYTES, bl);
#pragma unroll
        for (int half = 0; half < 2; half++) {
            const int ni = nb * 2 + half;
#pragma unroll
            for (int mi = 0; mi < 2; mi++) {
                mma_bf16(acc[mi][ni], &ah[mi * 4], bh[half], bh[half + 2]);
                mma_bf16(acc[mi][ni], &ah[mi * 4], bl[half], bl[half + 2]);
                mma_bf16(acc[mi][ni], &al[mi * 4], bh[half], bh[half + 2]);
            }
        }
    }
}

// K=128 pass, A pre-split bf16 (no in-loop conversion)
__device__ __forceinline__ void mma_pass_bf(const uint2* __restrict__ A, int m0,
                                            uint32_t sb, int wid, int lane,
                                            float acc[2][8][4])
{
    const int wm = wid & 3, wn = wid >> 2;
    const uint32_t lrow = (uint32_t)((lane & 15) * LDB + (lane >> 4) * 16);
    const uint32_t bBase = sb + wn * 64 * LDB + lrow;
    const int row0 = m0 + wm * 32;

    uint2 av[8];
    load_A_bf(A, row0, 0, lane, av);
#pragma unroll
    for (int ks = 0; ks < 8; ks++) {
        uint32_t ah[8], al[8];
#pragma unroll
        for (int i = 0; i < 8; i++) { ah[i] = av[i].x; al[i] = av[i].y; }
        if (ks < 7) load_A_bf(A, row0, (ks + 1) * 8, lane, av);
        mma_block(ah, al, bBase, (uint32_t)(ks * 32), acc);
    }
}

// K=128 pass, A fp32 with in-loop split (h_in embed, agg)
template<bool GUARD>
__device__ __forceinline__ void mma_pass_f32(const float* __restrict__ A, int m0,
                                             uint32_t sb, int wid, int lane,
                                             float acc[2][8][4])
{
    const int wm = wid & 3, wn = wid >> 2;
    const uint32_t lrow = (uint32_t)((lane & 15) * LDB + (lane >> 4) * 16);
    const uint32_t bBase = sb + wn * 64 * LDB + lrow;
    const int row0 = m0 + wm * 32;

    float2 av[8];
    load_A_raw<GUARD>(A, row0, 0, lane, av);
#pragma unroll
    for (int ks = 0; ks < 8; ks++) {
        uint32_t ah[8], al[8];
#pragma unroll
        for (int i = 0; i < 8; i++) ah[i] = pack_hi_lo(av[i].x, av[i].y, al[i]);
        if (ks < 7) load_A_raw<GUARD>(A, row0, (ks + 1) * 16, lane, av);
        mma_block(ah, al, bBase, (uint32_t)(ks * 32), acc);
    }
}

__device__ __forceinline__ void zero_acc(float acc[2][8][4]) {
#pragma unroll
    for (int mi = 0; mi < 2; mi++)
#pragma unroll
        for (int ni = 0; ni < 8; ni++)
#pragma unroll
            for (int j = 0; j < 4; j++) acc[mi][ni][j] = 0.f;
}

// ---------------------------------------------------------------------------
// Weight prep: 33 fp32 [K=128][N=128] blocks -> bf16 hi/lo padded [n][k] images
// slots: 0 = W_embed; per layer l: 1+8l+{0..2}=Wm{s,r,e}, {3..5}=We{s,r,e}, {6,7}=Wh{a,b}
// ---------------------------------------------------------------------------
__global__ __launch_bounds__(256)
void prep_weights(const float* __restrict__ W_embed, const float* __restrict__ Wm,
                  const float* __restrict__ Wh, const float* __restrict__ We)
{
    int t = blockIdx.x;
    const float* src;
    if (t == 0) src = W_embed;
    else {
        int tt = t - 1, l = tt >> 3, j = tt & 7;
        if (j < 3)      src = Wm + (size_t)l * 384 * HID + j * 16384;
        else if (j < 6) src = We + (size_t)l * 384 * HID + (j - 3) * 16384;
        else            src = Wh + (size_t)l * 256 * HID + (j - 6) * 16384;
    }
    char* dst = (char*)(g_Bw + (size_t)t * 4352);
    for (int i = threadIdx.x; i < 16384; i += 256) {
        int k = i >> 7, n = i & 127;
        float v = src[i];
        __nv_bfloat16 h = __float2bfloat16_rn(v);
        __nv_bfloat16 lo = __float2bfloat16_rn(v - __bfloat162float(h));
        uint32_t off = (uint32_t)(n * LDB + k * 2);
        *(__nv_bfloat16*)(dst + off) = h;
        *(__nv_bfloat16*)(dst + TILE_BYTES + off) = lo;
    }
}

// ---------------------------------------------------------------------------
// proj_gemm: grid (4, GY). P[:, y*128:(y+1)*128] = h @ Wblock[y], m grid-stride
// ---------------------------------------------------------------------------
__global__ __launch_bounds__(GT, 2)
void proj_gemm(const uint2* __restrict__ A, int sbase, float* __restrict__ C)
{
    extern __shared__ char smem[];
    uint32_t sb = smem_u32(smem);
    const int tid = threadIdx.x, wid = tid >> 5, lane = tid & 31;
    const int y = blockIdx.x;
    const int wm = wid & 3, wn = wid >> 2;
    const int r4 = lane >> 2, c2 = (lane & 3) * 2;

    stage_B(sbase + ((y < 2) ? y : y + 1), tid, smem);
    __syncthreads();

    for (int m0 = blockIdx.y * 128; m0 < N_PAD; m0 += gridDim.y * 128) {
        float acc[2][8][4];
        zero_acc(acc);
        mma_pass_bf(A, m0, sb, wid, lane, acc);

#pragma unroll
        for (int mi = 0; mi < 2; mi++) {
#pragma unroll
            for (int jh = 0; jh < 2; jh++) {
                int row = m0 + wm * 32 + mi * 16 + jh * 8 + r4;
                float* Cp = C + (size_t)row * 512 + y * 128;
#pragma unroll
                for (int ni = 0; ni < 8; ni++) {
                    int col = wn * 64 + ni * 8 + c2;
                    *(float2*)(Cp + col) = make_float2(acc[mi][ni][jh * 2 + 0],
                                                       acc[mi][ni][jh * 2 + 1]);
                }
            }
        }
    }
}

// ---------------------------------------------------------------------------
// embed_gemm: C_bf = h_in(fp32, guarded) @ B0 + bias   (m grid-stride)
// ---------------------------------------------------------------------------
__global__ __launch_bounds__(GT, 2)
void embed_gemm(const float* __restrict__ A, int slot,
                const float* __restrict__ bias, uint2* __restrict__ C)
{
    extern __shared__ char smem[];
    uint32_t sb = smem_u32(smem);
    const int tid = threadIdx.x, wid = tid >> 5, lane = tid & 31;
    const int wm = wid & 3, wn = wid >> 2;
    const int r4 = lane >> 2, c2 = (lane & 3) * 2;

    stage_B(slot, tid, smem);
    __syncthreads();

    for (int m0 = blockIdx.x * 128; m0 < N_PAD; m0 += gridDim.x * 128) {
        float acc[2][8][4];
        zero_acc(acc);
        mma_pass_f32<true>(A, m0, sb, wid, lane, acc);

#pragma unroll
        for (int mi = 0; mi < 2; mi++) {
#pragma unroll
            for (int jh = 0; jh < 2; jh++) {
                int row = m0 + wm * 32 + mi * 16 + jh * 8 + r4;
                uint2* Cp = C + (size_t)row * 64;
#pragma unroll
                for (int ni = 0; ni < 8; ni++) {
                    int col = wn * 64 + ni * 8 + c2;
                    float2 b = *(const float2*)(bias + col);
                    Cp[col >> 1] = pack_pair(acc[mi][ni][jh * 2 + 0] + b.x,
                                             acc[mi][ni][jh * 2 + 1] + b.y);
                }
            }
        }
    }
}

// ---------------------------------------------------------------------------
// hnew_gemm: C_bf = h_bf @ Wh_a + agg(fp32) @ Wh_b + bias   (m grid-stride)
// ---------------------------------------------------------------------------
__global__ __launch_bounds__(GT, 2)
void hnew_gemm(const uint2* __restrict__ A1, int slot1,
               const float* __restrict__ A2, int slot2,
               const float* __restrict__ bias, uint2* __restrict__ C)
{
    extern __shared__ char smem[];
    uint32_t sb = smem_u32(smem);
    const int tid = threadIdx.x, wid = tid >> 5, lane = tid & 31;
    const int wm = wid & 3, wn = wid >> 2;
    const int r4 = lane >> 2, c2 = (lane & 3) * 2;

    for (int m0 = blockIdx.x * 128; m0 < N_PAD; m0 += gridDim.x * 128) {
        __syncthreads();
        stage_B(slot1, tid, smem);
        __syncthreads();
        float acc[2][8][4];
        zero_acc(acc);
        mma_pass_bf(A1, m0, sb, wid, lane, acc);

        __syncthreads();
        stage_B(slot2, tid, smem);
        __syncthreads();
        mma_pass_f32<false>(A2, m0, sb, wid, lane, acc);

#pragma unroll
        for (int mi = 0; mi < 2; mi++) {
#pragma unroll
            for (int jh = 0; jh < 2; jh++) {
                int row = m0 + wm * 32 + mi * 16 + jh * 8 + r4;
                uint2* Cp = C + (size_t)row * 64;
#pragma unroll
                for (int ni = 0; ni < 8; ni++) {
                    int col = wn * 64 + ni * 8 + c2;
                    float2 b = *(const float2*)(bias + col);
                    Cp[col >> 1] = pack_pair(acc[mi][ni][jh * 2 + 0] + b.x,
                                             acc[mi][ni][jh * 2 + 1] + b.y);
                }
            }
        }
    }
}

// ---------------------------------------------------------------------------
// edge_gemm: grid (2, GY), m grid-stride
//  x==0: msg = e@Wm_e + bm + P[s,0:128] + P[r,128:256]  -> red.add agg[r]
//  x==1: e'  = e@We_e + be + P[s,256:384] + P[r,384:512] -> e_out (bf pair)
// ---------------------------------------------------------------------------
__global__ __launch_bounds__(GT, 2)
void edge_gemm(const uint2* __restrict__ E_in, int slot_m, int slot_e,
               const float* __restrict__ bm, const float* __restrict__ be,
               const float* __restrict__ P,
               const int* __restrict__ send, const int* __restrict__ rec,
               float* __restrict__ agg, uint2* __restrict__ e_out)
{
    extern __shared__ char smem[];
    uint32_t sb = smem_u32(smem);
    const int tid = threadIdx.x, wid = tid >> 5, lane = tid & 31;
    const int which = blockIdx.x;
    const int wm = wid & 3, wn = wid >> 2;
    const int r4 = lane >> 2, c2 = (lane & 3) * 2;

    stage_B(which ? slot_e : slot_m, tid, smem);
    __syncthreads();

    for (int m0 = blockIdx.y * 128; m0 < N_EDGES; m0 += gridDim.y * 128) {
        float acc[2][8][4];
        zero_acc(acc);
        mma_pass_bf(E_in, m0, sb, wid, lane, acc);

        if (which == 0) {
#pragma unroll
            for (int mi = 0; mi < 2; mi++) {
#pragma unroll
                for (int jh = 0; jh < 2; jh++) {
                    int row = m0 + wm * 32 + mi * 16 + jh * 8 + r4;
                    int s = send[row], r = rec[row];
                    const float* Ps = P + (size_t)s * 512;
                    const float* Pr = P + (size_t)r * 512 + 128;
                    float* ap = agg + (size_t)r * HID;
#pragma unroll
                    for (int ni = 0; ni < 8; ni++) {
                        int col = wn * 64 + ni * 8 + c2;
                        float2 b = *(const float2*)(bm + col);
                        float2 p = *(const float2*)(Ps + col);
                        float2 q = *(const float2*)(Pr + col);
                        red_add_v2(ap + col,
                                   acc[mi][ni][jh * 2 + 0] + b.x + p.x + q.x,
                                   acc[mi][ni][jh * 2 + 1] + b.y + p.y + q.y);
                    }
                }
            }
        } else {
#pragma unroll
            for (int mi = 0; mi < 2; mi++) {
#pragma unroll
                for (int jh = 0; jh < 2; jh++) {
                    int row = m0 + wm * 32 + mi * 16 + jh * 8 + r4;
                    int s = send[row], r = rec[row];
                    const float* Ps = P + (size_t)s * 512 + 256;
                    const float* Pr = P + (size_t)r * 512 + 384;
                    uint2* op = e_out + (size_t)row * 64;
#pragma unroll
                    for (int ni = 0; ni < 8; ni++) {
                        int col = wn * 64 + ni * 8 + c2;
                        float2 b = *(const float2*)(be + col);
                        float2 p = *(const float2*)(Ps + col);
                        float2 q = *(const float2*)(Pr + col);
                        op[col >> 1] = pack_pair(acc[mi][ni][jh * 2 + 0] + b.x + p.x + q.x,
                                                 acc[mi][ni][jh * 2 + 1] + b.y + p.y + q.y);
                    }
                }
            }
        }
    }
}

// ---------------------------------------------------------------------------
// Edge embedding: e0_bf = E[:,0:16] @ W[16,128] + b  (writes bf pairs)
// 128 threads: 2 edges per block-iter, 64 col-pairs each
// ---------------------------------------------------------------------------
__global__ __launch_bounds__(128)
void embed_e_kernel(const float* __restrict__ e_in, const float* __restrict__ W,
                    const float* __restrict__ b, uint2* __restrict__ out)
{
    __shared__ float Ws[16 * 128];
    __shared__ float bs[128];
    for (int i = threadIdx.x; i < 16 * 128; i += blockDim.x) Ws[i] = W[i];
    if (threadIdx.x < 128) bs[threadIdx.x] = b[threadIdx.x];
    __syncthreads();
    const int sub = threadIdx.x >> 6;
    const int cp = threadIdx.x & 63;
    const int c0 = cp * 2;
    for (int k = blockIdx.x * 2 + sub; k < N_EDGES; k += gridDim.x * 2) {
        const float* er = e_in + (size_t)k * 16;
        float a0 = bs[c0], a1 = bs[c0 + 1];
#pragma unroll
        for (int j = 0; j < 16; j++) {
            float e = er[j];
            a0 += e * Ws[j * 128 + c0];
            a1 += e * Ws[j * 128 + c0 + 1];
        }
        out[(size_t)k * 64 + cp] = pack_pair(a0, a1);
    }
}

// ---------------------------------------------------------------------------
// Global add-pool from bf pair storage: val = hi + lo
// ---------------------------------------------------------------------------
__global__ __launch_bounds__(128)
void pool_kernel(const uint2* __restrict__ h, const int* __restrict__ batch,
                 float* __restrict__ out)
{
    const int n = blockIdx.x;
    const int c = threadIdx.x;
    const int g = batch[n];
    uint2 v = h[(size_t)n * 64 + (c >> 1)];
    uint32_t sh = (c & 1) ? 16 : 0;
    float hi = __bfloat162float(__ushort_as_bfloat16((unsigned short)((v.x >> sh) & 0xFFFF)));
    float lo = __bfloat162float(__ushort_as_bfloat16((unsigned short)((v.y >> sh) & 0xFFFF)));
    atomicAdd(&out[(size_t)g * HID + c], hi + lo);
}

// ---------------------------------------------------------------------------
// Launch
// ---------------------------------------------------------------------------
extern "C" void kernel_launch(void* const* d_in, const int* in_sizes, int n_in,
                              void* d_out, int out_size)
{
    const float* h_in     = (const float*)d_in[0];
    const float* e_in     = (const float*)d_in[1];
    const int*   edge_idx = (const int*)  d_in[2];
    const int*   batch    = (const int*)  d_in[3];
    const float* W_embed  = (const float*)d_in[4];
    const float* b_embed  = (const float*)d_in[5];
    const float* W_eembed = (const float*)d_in[6];
    const float* b_eembed = (const float*)d_in[7];
    const float* Wm       = (const float*)d_in[8];
    const float* bm       = (const float*)d_in[9];
    const float* Wh       = (const float*)d_in[10];
    const float* bh       = (const float*)d_in[11];
    const float* We       = (const float*)d_in[12];
    const float* be       = (const float*)d_in[13];
    float*       out      = (float*)d_out;

    cudaFuncSetAttribute(proj_gemm,  cudaFuncAttributeMaxDynamicSharedMemorySize, SMEM_SZ);
    cudaFuncSetAttribute(embed_gemm, cudaFuncAttributeMaxDynamicSharedMemorySize, SMEM_SZ);
    cudaFuncSetAttribute(hnew_gemm,  cudaFuncAttributeMaxDynamicSharedMemorySize, SMEM_SZ);
    cudaFuncSetAttribute(edge_gemm,  cudaFuncAttributeMaxDynamicSharedMemorySize, SMEM_SZ);

    uint2 *hbuf, *ebuf;
    float *Pp, *aggp;
    cudaGetSymbolAddress((void**)&hbuf, g_hbf);
    cudaGetSymbolAddress((void**)&ebuf, g_ebf);
    cudaGetSymbolAddress((void**)&Pp,   g_P);
    cudaGetSymbolAddress((void**)&aggp, g_agg);

    uint2* hb[2] = { hbuf, hbuf + (size_t)N_PAD * 64 };
    uint2* eb[2] = { ebuf, ebuf + (size_t)N_EDGES * 64 };
    const int* send = edge_idx;
    const int* rec  = edge_idx + N_EDGES;

    // Weight prep + embeddings
    prep_weights<<<33, 256>>>(W_embed, Wm, Wh, We);
    embed_e_kernel<<<2048, 128>>>(e_in, W_eembed, b_eembed, eb[0]);
    embed_gemm<<<296, GT, SMEM_SZ>>>(h_in, 0, b_embed, hb[0]);

    int cur = 0;
    for (int l = 0; l < N_LAYERS; l++) {
        int sbase = 1 + l * 8;
        const float* bm_l = bm + (size_t)l * HID;
        const float* bh_l = bh + (size_t)l * HID;
        const float* be_l = be + (size_t)l * HID;
        uint2* hcur = hb[cur];
        uint2* ecur = eb[cur];
        uint2* hnxt = hb[1 - cur];
        uint2* enxt = eb[1 - cur];

        // P = h @ [Wm_s | Wm_r | We_s | We_r]  -> [N, 512] fp32
        proj_gemm<<<dim3(4, 148), GT, SMEM_SZ>>>(hcur, sbase, Pp);

        cudaMemsetAsync(aggp, 0, (size_t)N_PAD * HID * sizeof(float));

        // Fused edge GEMMs: x=0 message+scatter, x=1 edge update (B staged once/CTA)
        edge_gemm<<<dim3(2, 592), GT, SMEM_SZ>>>(
            ecur, sbase + 2, sbase + 5, bm_l, be_l, Pp, send, rec, aggp, enxt);

        // h_new = [h | agg] @ Wh + bh
        hnew_gemm<<<296, GT, SMEM_SZ>>>(hcur, sbase + 6, aggp, sbase + 7, bh_l, hnxt);

        cur = 1 - cur;
    }

    cudaMemsetAsync(d_out, 0, (size_t)NUM_GRAPHS * HID * sizeof(float));
    pool_kernel<<<N_NODES, 128>>>(hb[cur], batch, out);
}

// round 8
// speedup vs baseline: 1.1891x; 1.1891x over previous
#include <cuda_runtime.h>
#include <cuda_fp16.h>
#include <cstdint>

#define N_NODES 40000
#define N_PAD   40064   // 313 * 128
#define N_EDGES 640000
#define HID 128
#define N_LAYERS 4
#define NUM_GRAPHS 256

#define GT 256          // 8 warps per GEMM CTA

// B tile in SMEM: padded row-major [n][k] fp16, 128 rows x 272B (single plane)
#define LDB 272
#define TILE_BYTES 34816
#define SMEM_1 34816
#define SMEM_2 69632

// ---------------------------------------------------------------------------
// Scratch. h and e live as pre-split fp16 hi/lo, interleaved per col-pair:
//   buf[row*64 + col/2] = { hi_pair(fp16x2), lo_pair(fp16x2) }
// ---------------------------------------------------------------------------
__device__ uint2 g_hbf[2][(size_t)N_PAD * 64];
__device__ uint2 g_ebf[2][(size_t)N_EDGES * 64];
__device__ float g_P[(size_t)N_PAD * 4 * HID];     // [N,512]: hWm_s | hWm_r | hWe_s | hWe_r (fp32)
__device__ float g_agg[(size_t)N_PAD * HID];       // fp32 scatter-add target
// 33 weight slots: single fp16 image (34816 B = 2176 uint4), padded [n][k]
__device__ uint4 g_Bw[(size_t)33 * 2176];

// ---------------------------------------------------------------------------
// PTX helpers (baseline ISA only)
// ---------------------------------------------------------------------------
__device__ __forceinline__ uint32_t smem_u32(const void* p) {
    uint32_t a;
    asm("{ .reg .u64 t; cvta.to.shared.u64 t, %1; cvt.u32.u64 %0, t; }" : "=r"(a) : "l"(p));
    return a;
}
__device__ __forceinline__ void red_add_v2(float* addr, float a, float b) {
    asm volatile("red.global.add.v2.f32 [%0], {%1, %2};"
                 :: "l"(addr), "f"(a), "f"(b) : "memory");
}
__device__ __forceinline__ void ldsm_x4(uint32_t addr, uint32_t r[4]) {
    asm volatile("ldmatrix.sync.aligned.m8n8.x4.shared.b16 {%0,%1,%2,%3}, [%4];"
                 : "=r"(r[0]), "=r"(r[1]), "=r"(r[2]), "=r"(r[3]) : "r"(addr));
}
__device__ __forceinline__ void mma_f16(float c[4], const uint32_t a[4], uint32_t b0, uint32_t b1) {
    asm volatile("mma.sync.aligned.m16n8k16.row.col.f32.f16.f16.f32 "
                 "{%0,%1,%2,%3}, {%4,%5,%6,%7}, {%8,%9}, {%0,%1,%2,%3};"
                 : "+f"(c[0]), "+f"(c[1]), "+f"(c[2]), "+f"(c[3])
                 : "r"(a[0]), "r"(a[1]), "r"(a[2]), "r"(a[3]), "r"(b0), "r"(b1));
}
__device__ __forceinline__ uint32_t pack_hi_lo(float a, float b, uint32_t& lo_out) {
    __half ha = __float2half_rn(a), hb = __float2half_rn(b);
    float ra = a - __half2float(ha), rb = b - __half2float(hb);
    __half la = __float2half_rn(ra), lb = __float2half_rn(rb);
    lo_out = (uint32_t)__half_as_ushort(la) | ((uint32_t)__half_as_ushort(lb) << 16);
    return (uint32_t)__half_as_ushort(ha) | ((uint32_t)__half_as_ushort(hb) << 16);
}
__device__ __forceinline__ uint2 pack_pair(float x, float y) {
    uint2 o; o.x = pack_hi_lo(x, y, o.y); return o;
}

// Stage B: copy one fp16 image (34816 B = 2176 uint4) into SMEM at byte offset
__device__ __forceinline__ void stage_B(int slot, int tid, char* smem, int off)
{
    const uint4* src = g_Bw + (size_t)slot * 2176;
    uint4* dst = (uint4*)(smem + off);
#pragma unroll
    for (int i = 0; i < 9; i++) {
        int idx = tid + i * 256;
        if (idx < 2176) dst[idx] = src[idx];
    }
}

// ---------------------------------------------------------------------------
// A loaders. Fragment slot av[mi*4 + jh + 2*jc] covers
//   row = row0 + mi*16 + jh*8 + (lane>>2), colpair = k0/2 + (lane&3) + jc*4
// ---------------------------------------------------------------------------
__device__ __forceinline__ void load_A_bf(const uint2* __restrict__ A, int row0, int k0p,
                                          int lane, uint2 av[8])
{
    const int r = row0 + (lane >> 2);
    const int cp = k0p + (lane & 3);
#pragma unroll
    for (int mi = 0; mi < 2; mi++)
#pragma unroll
        for (int p = 0; p < 4; p++) {
            int row = r + mi * 16 + (p & 1) * 8;
            av[mi * 4 + p] = A[(size_t)row * 64 + cp + (p >> 1) * 4];
        }
}
template<bool GUARD>
__device__ __forceinline__ void load_A_raw(const float* __restrict__ A, int row0, int k0,
                                           int lane, float2 av[8])
{
    const int r = row0 + (lane >> 2);
    const int c = k0 + (lane & 3) * 2;
#pragma unroll
    for (int mi = 0; mi < 2; mi++)
#pragma unroll
        for (int jh = 0; jh < 2; jh++) {
            int row = r + mi * 16 + jh * 8;
            const float* rp = A + (size_t)row * HID + c;
#pragma unroll
            for (int jc = 0; jc < 2; jc++) {
                float2 v = make_float2(0.f, 0.f);
                if (!GUARD || row < N_NODES) v = *(const float2*)(rp + jc * 8);
                av[mi * 4 + jh + 2 * jc] = v;
            }
        }
}

// ---------------------------------------------------------------------------
// 32-MMA inner block: 2 products (Ah@B + Al@B), B single fp16 plane
// ---------------------------------------------------------------------------
__device__ __forceinline__ void mma_block(const uint32_t ah[8], const uint32_t al[8],
                                          uint32_t bBase, uint32_t ko, float acc[2][8][4])
{
#pragma unroll
    for (int nb = 0; nb < 4; nb++) {
        uint32_t bh[4];
        ldsm_x4(bBase + nb * 16 * LDB + ko, bh);
#pragma unroll
        for (int half = 0; half < 2; half++) {
            const int ni = nb * 2 + half;
#pragma unroll
            for (int mi = 0; mi < 2; mi++) {
                mma_f16(acc[mi][ni], &ah[mi * 4], bh[half], bh[half + 2]);
                mma_f16(acc[mi][ni], &al[mi * 4], bh[half], bh[half + 2]);
            }
        }
    }
}

// K=128 pass, A pre-split fp16 (no in-loop conversion). bOff = SMEM byte offset of B image.
__device__ __forceinline__ void mma_pass_bf(const uint2* __restrict__ A, int m0,
                                            uint32_t sb, int bOff, int wid, int lane,
                                            float acc[2][8][4])
{
    const int wm = wid & 3, wn = wid >> 2;
    const uint32_t lrow = (uint32_t)((lane & 15) * LDB + (lane >> 4) * 16);
    const uint32_t bBase = sb + bOff + wn * 64 * LDB + lrow;
    const int row0 = m0 + wm * 32;

    uint2 av[8];
    load_A_bf(A, row0, 0, lane, av);
#pragma unroll
    for (int ks = 0; ks < 8; ks++) {
        uint32_t ah[8], al[8];
#pragma unroll
        for (int i = 0; i < 8; i++) { ah[i] = av[i].x; al[i] = av[i].y; }
        if (ks < 7) load_A_bf(A, row0, (ks + 1) * 8, lane, av);
        mma_block(ah, al, bBase, (uint32_t)(ks * 32), acc);
    }
}

// K=128 pass, A fp32 with in-loop split (h_in embed, agg)
template<bool GUARD>
__device__ __forceinline__ void mma_pass_f32(const float* __restrict__ A, int m0,
                                             uint32_t sb, int bOff, int wid, int lane,
                                             float acc[2][8][4])
{
    const int wm = wid & 3, wn = wid >> 2;
    const uint32_t lrow = (uint32_t)((lane & 15) * LDB + (lane >> 4) * 16);
    const uint32_t bBase = sb + bOff + wn * 64 * LDB + lrow;
    const int row0 = m0 + wm * 32;

    float2 av[8];
    load_A_raw<GUARD>(A, row0, 0, lane, av);
#pragma unroll
    for (int ks = 0; ks < 8; ks++) {
        uint32_t ah[8], al[8];
#pragma unroll
        for (int i = 0; i < 8; i++) ah[i] = pack_hi_lo(av[i].x, av[i].y, al[i]);
        if (ks < 7) load_A_raw<GUARD>(A, row0, (ks + 1) * 16, lane, av);
        mma_block(ah, al, bBase, (uint32_t)(ks * 32), acc);
    }
}

__device__ __forceinline__ void zero_acc(float acc[2][8][4]) {
#pragma unroll
    for (int mi = 0; mi < 2; mi++)
#pragma unroll
        for (int ni = 0; ni < 8; ni++)
#pragma unroll
            for (int j = 0; j < 4; j++) acc[mi][ni][j] = 0.f;
}

// ---------------------------------------------------------------------------
// Weight prep: 33 fp32 [K=128][N=128] blocks -> single fp16 padded [n][k] images
// slots: 0 = W_embed; per layer l: 1+8l+{0..2}=Wm{s,r,e}, {3..5}=We{s,r,e}, {6,7}=Wh{a,b}
// ---------------------------------------------------------------------------
__global__ __launch_bounds__(256)
void prep_weights(const float* __restrict__ W_embed, const float* __restrict__ Wm,
                  const float* __restrict__ Wh, const float* __restrict__ We)
{
    int t = blockIdx.x;
    const float* src;
    if (t == 0) src = W_embed;
    else {
        int tt = t - 1, l = tt >> 3, j = tt & 7;
        if (j < 3)      src = Wm + (size_t)l * 384 * HID + j * 16384;
        else if (j < 6) src = We + (size_t)l * 384 * HID + (j - 3) * 16384;
        else            src = Wh + (size_t)l * 256 * HID + (j - 6) * 16384;
    }
    char* dst = (char*)(g_Bw + (size_t)t * 2176);
    for (int i = threadIdx.x; i < 16384; i += 256) {
        int k = i >> 7, n = i & 127;
        *(__half*)(dst + (uint32_t)(n * LDB + k * 2)) = __float2half_rn(src[i]);
    }
}

// ---------------------------------------------------------------------------
// proj_gemm: grid (4, GY). P[:, y*128:(y+1)*128] = h @ Wblock[y], m grid-stride
// ---------------------------------------------------------------------------
__global__ __launch_bounds__(GT, 2)
void proj_gemm(const uint2* __restrict__ A, int sbase, float* __restrict__ C)
{
    extern __shared__ char smem[];
    uint32_t sb = smem_u32(smem);
    const int tid = threadIdx.x, wid = tid >> 5, lane = tid & 31;
    const int y = blockIdx.x;
    const int wm = wid & 3, wn = wid >> 2;
    const int r4 = lane >> 2, c2 = (lane & 3) * 2;

    stage_B(sbase + ((y < 2) ? y : y + 1), tid, smem, 0);
    __syncthreads();

    for (int m0 = blockIdx.y * 128; m0 < N_PAD; m0 += gridDim.y * 128) {
        float acc[2][8][4];
        zero_acc(acc);
        mma_pass_bf(A, m0, sb, 0, wid, lane, acc);

#pragma unroll
        for (int mi = 0; mi < 2; mi++) {
#pragma unroll
            for (int jh = 0; jh < 2; jh++) {
                int row = m0 + wm * 32 + mi * 16 + jh * 8 + r4;
                float* Cp = C + (size_t)row * 512 + y * 128;
#pragma unroll
                for (int ni = 0; ni < 8; ni++) {
                    int col = wn * 64 + ni * 8 + c2;
                    *(float2*)(Cp + col) = make_float2(acc[mi][ni][jh * 2 + 0],
                                                       acc[mi][ni][jh * 2 + 1]);
                }
            }
        }
    }
}

// ---------------------------------------------------------------------------
// embed_gemm: C_bf = h_in(fp32, guarded) @ B0 + bias   (m grid-stride)
// ---------------------------------------------------------------------------
__global__ __launch_bounds__(GT, 2)
void embed_gemm(const float* __restrict__ A, int slot,
                const float* __restrict__ bias, uint2* __restrict__ C)
{
    extern __shared__ char smem[];
    uint32_t sb = smem_u32(smem);
    const int tid = threadIdx.x, wid = tid >> 5, lane = tid & 31;
    const int wm = wid & 3, wn = wid >> 2;
    const int r4 = lane >> 2, c2 = (lane & 3) * 2;

    stage_B(slot, tid, smem, 0);
    __syncthreads();

    for (int m0 = blockIdx.x * 128; m0 < N_PAD; m0 += gridDim.x * 128) {
        float acc[2][8][4];
        zero_acc(acc);
        mma_pass_f32<true>(A, m0, sb, 0, wid, lane, acc);

#pragma unroll
        for (int mi = 0; mi < 2; mi++) {
#pragma unroll
            for (int jh = 0; jh < 2; jh++) {
                int row = m0 + wm * 32 + mi * 16 + jh * 8 + r4;
                uint2* Cp = C + (size_t)row * 64;
#pragma unroll
                for (int ni = 0; ni < 8; ni++) {
                    int col = wn * 64 + ni * 8 + c2;
                    float2 b = *(const float2*)(bias + col);
                    Cp[col >> 1] = pack_pair(acc[mi][ni][jh * 2 + 0] + b.x,
                                             acc[mi][ni][jh * 2 + 1] + b.y);
                }
            }
        }
    }
}

// ---------------------------------------------------------------------------
// hnew_gemm: C_bf = h_bf @ Wh_a + agg(fp32) @ Wh_b + bias. Both B images resident.
// ---------------------------------------------------------------------------
__global__ __launch_bounds__(GT, 2)
void hnew_gemm(const uint2* __restrict__ A1, int slot1,
               const float* __restrict__ A2, int slot2,
               const float* __restrict__ bias, uint2* __restrict__ C)
{
    extern __shared__ char smem[];
    uint32_t sb = smem_u32(smem);
    const int tid = threadIdx.x, wid = tid >> 5, lane = tid & 31;
    const int wm = wid & 3, wn = wid >> 2;
    const int r4 = lane >> 2, c2 = (lane & 3) * 2;

    stage_B(slot1, tid, smem, 0);
    stage_B(slot2, tid, smem, TILE_BYTES);
    __syncthreads();

    for (int m0 = blockIdx.x * 128; m0 < N_PAD; m0 += gridDim.x * 128) {
        float acc[2][8][4];
        zero_acc(acc);
        mma_pass_bf(A1, m0, sb, 0, wid, lane, acc);
        mma_pass_f32<false>(A2, m0, sb, TILE_BYTES, wid, lane, acc);

#pragma unroll
        for (int mi = 0; mi < 2; mi++) {
#pragma unroll
            for (int jh = 0; jh < 2; jh++) {
                int row = m0 + wm * 32 + mi * 16 + jh * 8 + r4;
                uint2* Cp = C + (size_t)row * 64;
#pragma unroll
                for (int ni = 0; ni < 8; ni++) {
                    int col = wn * 64 + ni * 8 + c2;
                    float2 b = *(const float2*)(bias + col);
                    Cp[col >> 1] = pack_pair(acc[mi][ni][jh * 2 + 0] + b.x,
                                             acc[mi][ni][jh * 2 + 1] + b.y);
                }
            }
        }
    }
}

// ---------------------------------------------------------------------------
// edge_gemm: grid (2, GY), m grid-stride
//  x==0: msg = e@Wm_e + bm + P[s,0:128] + P[r,128:256]  -> red.add agg[r]
//  x==1: e'  = e@We_e + be + P[s,256:384] + P[r,384:512] -> e_out (fp16 pair)
// ---------------------------------------------------------------------------
__global__ __launch_bounds__(GT, 2)
void edge_gemm(const uint2* __restrict__ E_in, int slot_m, int slot_e,
               const float* __restrict__ bm, const float* __restrict__ be,
               const float* __restrict__ P,
               const int* __restrict__ send, const int* __restrict__ rec,
               float* __restrict__ agg, uint2* __restrict__ e_out)
{
    extern __shared__ char smem[];
    uint32_t sb = smem_u32(smem);
    const int tid = threadIdx.x, wid = tid >> 5, lane = tid & 31;
    const int which = blockIdx.x;
    const int wm = wid & 3, wn = wid >> 2;
    const int r4 = lane >> 2, c2 = (lane & 3) * 2;

    stage_B(which ? slot_e : slot_m, tid, smem, 0);
    __syncthreads();

    for (int m0 = blockIdx.y * 128; m0 < N_EDGES; m0 += gridDim.y * 128) {
        float acc[2][8][4];
        zero_acc(acc);
        mma_pass_bf(E_in, m0, sb, 0, wid, lane, acc);

        if (which == 0) {
#pragma unroll
            for (int mi = 0; mi < 2; mi++) {
#pragma unroll
                for (int jh = 0; jh < 2; jh++) {
                    int row = m0 + wm * 32 + mi * 16 + jh * 8 + r4;
                    int s = send[row], r = rec[row];
                    const float* Ps = P + (size_t)s * 512;
                    const float* Pr = P + (size_t)r * 512 + 128;
                    float* ap = agg + (size_t)r * HID;
#pragma unroll
                    for (int ni = 0; ni < 8; ni++) {
                        int col = wn * 64 + ni * 8 + c2;
                        float2 b = *(const float2*)(bm + col);
                        float2 p = *(const float2*)(Ps + col);
                        float2 q = *(const float2*)(Pr + col);
                        red_add_v2(ap + col,
                                   acc[mi][ni][jh * 2 + 0] + b.x + p.x + q.x,
                                   acc[mi][ni][jh * 2 + 1] + b.y + p.y + q.y);
                    }
                }
            }
        } else {
#pragma unroll
            for (int mi = 0; mi < 2; mi++) {
#pragma unroll
                for (int jh = 0; jh < 2; jh++) {
                    int row = m0 + wm * 32 + mi * 16 + jh * 8 + r4;
                    int s = send[row], r = rec[row];
                    const float* Ps = P + (size_t)s * 512 + 256;
                    const float* Pr = P + (size_t)r * 512 + 384;
                    uint2* op = e_out + (size_t)row * 64;
#pragma unroll
                    for (int ni = 0; ni < 8; ni++) {
                        int col = wn * 64 + ni * 8 + c2;
                        float2 b = *(const float2*)(be + col);
                        float2 p = *(const float2*)(Ps + col);
                        float2 q = *(const float2*)(Pr + col);
                        op[col >> 1] = pack_pair(acc[mi][ni][jh * 2 + 0] + b.x + p.x + q.x,
                                                 acc[mi][ni][jh * 2 + 1] + b.y + p.y + q.y);
                    }
                }
            }
        }
    }
}

// ---------------------------------------------------------------------------
// Edge embedding: e0_bf = E[:,0:16] @ W[16,128] + b  (writes fp16 pairs)
// ---------------------------------------------------------------------------
__global__ __launch_bounds__(128)
void embed_e_kernel(const float* __restrict__ e_in, const float* __restrict__ W,
                    const float* __restrict__ b, uint2* __restrict__ out)
{
    __shared__ float Ws[16 * 128];
    __shared__ float bs[128];
    for (int i = threadIdx.x; i < 16 * 128; i += blockDim.x) Ws[i] = W[i];
    if (threadIdx.x < 128) bs[threadIdx.x] = b[threadIdx.x];
    __syncthreads();
    const int sub = threadIdx.x >> 6;
    const int cp = threadIdx.x & 63;
    const int c0 = cp * 2;
    for (int k = blockIdx.x * 2 + sub; k < N_EDGES; k += gridDim.x * 2) {
        const float* er = e_in + (size_t)k * 16;
        float a0 = bs[c0], a1 = bs[c0 + 1];
#pragma unroll
        for (int j = 0; j < 16; j++) {
            float e = er[j];
            a0 += e * Ws[j * 128 + c0];
            a1 += e * Ws[j * 128 + c0 + 1];
        }
        out[(size_t)k * 64 + cp] = pack_pair(a0, a1);
    }
}

// ---------------------------------------------------------------------------
// Global add-pool from fp16 pair storage: val = hi + lo
// ---------------------------------------------------------------------------
__global__ __launch_bounds__(128)
void pool_kernel(const uint2* __restrict__ h, const int* __restrict__ batch,
                 float* __restrict__ out)
{
    const int n = blockIdx.x;
    const int c = threadIdx.x;
    const int g = batch[n];
    uint2 v = h[(size_t)n * 64 + (c >> 1)];
    uint32_t sh = (c & 1) ? 16 : 0;
    float hi = __half2float(__ushort_as_half((unsigned short)((v.x >> sh) & 0xFFFF)));
    float lo = __half2float(__ushort_as_half((unsigned short)((v.y >> sh) & 0xFFFF)));
    atomicAdd(&out[(size_t)g * HID + c], hi + lo);
}

// ---------------------------------------------------------------------------
// Launch
// ---------------------------------------------------------------------------
extern "C" void kernel_launch(void* const* d_in, const int* in_sizes, int n_in,
                              void* d_out, int out_size)
{
    const float* h_in     = (const float*)d_in[0];
    const float* e_in     = (const float*)d_in[1];
    const int*   edge_idx = (const int*)  d_in[2];
    const int*   batch    = (const int*)  d_in[3];
    const float* W_embed  = (const float*)d_in[4];
    const float* b_embed  = (const float*)d_in[5];
    const float* W_eembed = (const float*)d_in[6];
    const float* b_eembed = (const float*)d_in[7];
    const float* Wm       = (const float*)d_in[8];
    const float* bm       = (const float*)d_in[9];
    const float* Wh       = (const float*)d_in[10];
    const float* bh       = (const float*)d_in[11];
    const float* We       = (const float*)d_in[12];
    const float* be       = (const float*)d_in[13];
    float*       out      = (float*)d_out;

    cudaFuncSetAttribute(proj_gemm,  cudaFuncAttributeMaxDynamicSharedMemorySize, SMEM_1);
    cudaFuncSetAttribute(embed_gemm, cudaFuncAttributeMaxDynamicSharedMemorySize, SMEM_1);
    cudaFuncSetAttribute(hnew_gemm,  cudaFuncAttributeMaxDynamicSharedMemorySize, SMEM_2);
    cudaFuncSetAttribute(edge_gemm,  cudaFuncAttributeMaxDynamicSharedMemorySize, SMEM_1);

    uint2 *hbuf, *ebuf;
    float *Pp, *aggp;
    cudaGetSymbolAddress((void**)&hbuf, g_hbf);
    cudaGetSymbolAddress((void**)&ebuf, g_ebf);
    cudaGetSymbolAddress((void**)&Pp,   g_P);
    cudaGetSymbolAddress((void**)&aggp, g_agg);

    uint2* hb[2] = { hbuf, hbuf + (size_t)N_PAD * 64 };
    uint2* eb[2] = { ebuf, ebuf + (size_t)N_EDGES * 64 };
    const int* send = edge_idx;
    const int* rec  = edge_idx + N_EDGES;

    // Weight prep + embeddings
    prep_weights<<<33, 256>>>(W_embed, Wm, Wh, We);
    embed_e_kernel<<<2048, 128>>>(e_in, W_eembed, b_eembed, eb[0]);
    embed_gemm<<<296, GT, SMEM_1>>>(h_in, 0, b_embed, hb[0]);

    int cur = 0;
    for (int l = 0; l < N_LAYERS; l++) {
        int sbase = 1 + l * 8;
        const float* bm_l = bm + (size_t)l * HID;
        const float* bh_l = bh + (size_t)l * HID;
        const float* be_l = be + (size_t)l * HID;
        uint2* hcur = hb[cur];
        uint2* ecur = eb[cur];
        uint2* hnxt = hb[1 - cur];
        uint2* enxt = eb[1 - cur];

        // P = h @ [Wm_s | Wm_r | We_s | We_r]  -> [N, 512] fp32
        proj_gemm<<<dim3(4, 148), GT, SMEM_1>>>(hcur, sbase, Pp);

        cudaMemsetAsync(aggp, 0, (size_t)N_PAD * HID * sizeof(float));

        // Fused edge GEMMs: x=0 message+scatter, x=1 edge update (B staged once/CTA)
        edge_gemm<<<dim3(2, 592), GT, SMEM_1>>>(
            ecur, sbase + 2, sbase + 5, bm_l, be_l, Pp, send, rec, aggp, enxt);

        // h_new = [h | agg] @ Wh + bh
        hnew_gemm<<<296, GT, SMEM_2>>>(hcur, sbase + 6, aggp, sbase + 7, bh_l, hnxt);

        cur = 1 - cur;
    }

    cudaMemsetAsync(d_out, 0, (size_t)NUM_GRAPHS * HID * sizeof(float));
    pool_kernel<<<N_NODES, 128>>>(hb[cur], batch, out);
}

// round 9
// speedup vs baseline: 1.4901x; 1.2531x over previous
#include <cuda_runtime.h>
#include <cuda_fp16.h>
#include <cstdint>

#define N_NODES 40000
#define N_PAD   40064   // 313 * 128
#define N_EDGES 640000
#define HID 128
#define N_LAYERS 4
#define NUM_GRAPHS 256

#define GT 256          // 8 warps per GEMM CTA

// B tile in SMEM: padded row-major [n][k] fp16, 128 rows x 272B (single plane)
#define LDB 272
#define TILE_BYTES 34816
#define SMEM_1 34816
#define SMEM_2 69632

// ---------------------------------------------------------------------------
// Scratch. h and e live as fp16 hi/lo in fragment-quad layout:
//   row stride = 32 uint4 (512B). uint4 at [row*32 + ks*4 + i] =
//   { hi(cp), hi(cp+4), lo(cp), lo(cp+4) } with cp = ks*8 + i, i in [0,4)
// ---------------------------------------------------------------------------
__device__ uint4 g_hbf[2][(size_t)N_PAD * 32];
__device__ uint4 g_ebf[2][(size_t)N_EDGES * 32];
__device__ float g_P[(size_t)N_PAD * 4 * HID];     // [N,512]: hWm_s | hWm_r | hWe_s | hWe_r (fp32)
__device__ float g_agg[(size_t)N_PAD * HID];       // fp32 scatter-add target
__device__ int   g_deg[N_PAD];                     // in-degree (rec counts)
// 33 weight slots: single fp16 image (34816 B = 2176 uint4), padded [n][k]
__device__ uint4 g_Bw[(size_t)33 * 2176];

// ---------------------------------------------------------------------------
// PTX helpers (baseline ISA only)
// ---------------------------------------------------------------------------
__device__ __forceinline__ uint32_t smem_u32(const void* p) {
    uint32_t a;
    asm("{ .reg .u64 t; cvta.to.shared.u64 t, %1; cvt.u32.u64 %0, t; }" : "=r"(a) : "l"(p));
    return a;
}
__device__ __forceinline__ void red_add_v2(float* addr, float a, float b) {
    asm volatile("red.global.add.v2.f32 [%0], {%1, %2};"
                 :: "l"(addr), "f"(a), "f"(b) : "memory");
}
__device__ __forceinline__ void ldsm_x4(uint32_t addr, uint32_t r[4]) {
    asm volatile("ldmatrix.sync.aligned.m8n8.x4.shared.b16 {%0,%1,%2,%3}, [%4];"
                 : "=r"(r[0]), "=r"(r[1]), "=r"(r[2]), "=r"(r[3]) : "r"(addr));
}
__device__ __forceinline__ void mma_f16(float c[4], const uint32_t a[4], uint32_t b0, uint32_t b1) {
    asm volatile("mma.sync.aligned.m16n8k16.row.col.f32.f16.f16.f32 "
                 "{%0,%1,%2,%3}, {%4,%5,%6,%7}, {%8,%9}, {%0,%1,%2,%3};"
                 : "+f"(c[0]), "+f"(c[1]), "+f"(c[2]), "+f"(c[3])
                 : "r"(a[0]), "r"(a[1]), "r"(a[2]), "r"(a[3]), "r"(b0), "r"(b1));
}
__device__ __forceinline__ uint32_t pack_hi_lo(float a, float b, uint32_t& lo_out) {
    __half ha = __float2half_rn(a), hb = __float2half_rn(b);
    float ra = a - __half2float(ha), rb = b - __half2float(hb);
    __half la = __float2half_rn(ra), lb = __float2half_rn(rb);
    lo_out = (uint32_t)__half_as_ushort(la) | ((uint32_t)__half_as_ushort(lb) << 16);
    return (uint32_t)__half_as_ushort(ha) | ((uint32_t)__half_as_ushort(hb) << 16);
}

// Stage B: copy one fp16 image (34816 B = 2176 uint4) into SMEM at byte offset
__device__ __forceinline__ void stage_B(int slot, int tid, char* smem, int off)
{
    const uint4* src = g_Bw + (size_t)slot * 2176;
    uint4* dst = (uint4*)(smem + off);
#pragma unroll
    for (int i = 0; i < 9; i++) {
        int idx = tid + i * 256;
        if (idx < 2176) dst[idx] = src[idx];
    }
}

// ---------------------------------------------------------------------------
// A loaders
// ---------------------------------------------------------------------------
// Fragment-quad layout: one LDG.128 per row-slot (mi, jh).
__device__ __forceinline__ void load_A4(const uint4* __restrict__ A, int row0, int ks,
                                        int lane, uint4 av[4])
{
    const uint4* base = A + (size_t)(row0 + (lane >> 2)) * 32 + ks * 4 + (lane & 3);
#pragma unroll
    for (int mi = 0; mi < 2; mi++)
#pragma unroll
        for (int jh = 0; jh < 2; jh++)
            av[mi * 2 + jh] = base[(size_t)(mi * 16 + jh * 8) * 32];
}
// fp32 row-major loader (h_in embed, agg)
template<bool GUARD>
__device__ __forceinline__ void load_A_raw(const float* __restrict__ A, int row0, int k0,
                                           int lane, float2 av[8])
{
    const int r = row0 + (lane >> 2);
    const int c = k0 + (lane & 3) * 2;
#pragma unroll
    for (int mi = 0; mi < 2; mi++)
#pragma unroll
        for (int jh = 0; jh < 2; jh++) {
            int row = r + mi * 16 + jh * 8;
            const float* rp = A + (size_t)row * HID + c;
#pragma unroll
            for (int jc = 0; jc < 2; jc++) {
                float2 v = make_float2(0.f, 0.f);
                if (!GUARD || row < N_NODES) v = *(const float2*)(rp + jc * 8);
                av[mi * 4 + jh + 2 * jc] = v;
            }
        }
}

// ---------------------------------------------------------------------------
// 32-MMA inner block: 2 products (Ah@B + Al@B), B single fp16 plane
// ---------------------------------------------------------------------------
__device__ __forceinline__ void mma_block(const uint32_t ah[8], const uint32_t al[8],
                                          uint32_t bBase, uint32_t ko, float acc[2][8][4])
{
#pragma unroll
    for (int nb = 0; nb < 4; nb++) {
        uint32_t bh[4];
        ldsm_x4(bBase + nb * 16 * LDB + ko, bh);
#pragma unroll
        for (int half = 0; half < 2; half++) {
            const int ni = nb * 2 + half;
#pragma unroll
            for (int mi = 0; mi < 2; mi++) {
                mma_f16(acc[mi][ni], &ah[mi * 4], bh[half], bh[half + 2]);
                mma_f16(acc[mi][ni], &al[mi * 4], bh[half], bh[half + 2]);
            }
        }
    }
}

// K=128 pass, A in fragment-quad layout (no in-loop conversion)
__device__ __forceinline__ void mma_pass_bf(const uint4* __restrict__ A, int m0,
                                            uint32_t sb, int bOff, int wid, int lane,
                                            float acc[2][8][4])
{
    const int wm = wid & 3, wn = wid >> 2;
    const uint32_t lrow = (uint32_t)((lane & 15) * LDB + (lane >> 4) * 16);
    const uint32_t bBase = sb + bOff + wn * 64 * LDB + lrow;
    const int row0 = m0 + wm * 32;

    uint4 av[4];
    load_A4(A, row0, 0, lane, av);
#pragma unroll
    for (int ks = 0; ks < 8; ks++) {
        uint32_t ah[8], al[8];
#pragma unroll
        for (int s = 0; s < 4; s++) {
            const int mi = s >> 1, jh = s & 1;
            ah[mi * 4 + jh]     = av[s].x;
            ah[mi * 4 + jh + 2] = av[s].y;
            al[mi * 4 + jh]     = av[s].z;
            al[mi * 4 + jh + 2] = av[s].w;
        }
        if (ks < 7) load_A4(A, row0, ks + 1, lane, av);
        mma_block(ah, al, bBase, (uint32_t)(ks * 32), acc);
    }
}

// K=128 pass, A fp32 with in-loop split (h_in embed, agg)
template<bool GUARD>
__device__ __forceinline__ void mma_pass_f32(const float* __restrict__ A, int m0,
                                             uint32_t sb, int bOff, int wid, int lane,
                                             float acc[2][8][4])
{
    const int wm = wid & 3, wn = wid >> 2;
    const uint32_t lrow = (uint32_t)((lane & 15) * LDB + (lane >> 4) * 16);
    const uint32_t bBase = sb + bOff + wn * 64 * LDB + lrow;
    const int row0 = m0 + wm * 32;

    float2 av[8];
    load_A_raw<GUARD>(A, row0, 0, lane, av);
#pragma unroll
    for (int ks = 0; ks < 8; ks++) {
        uint32_t ah[8], al[8];
#pragma unroll
        for (int i = 0; i < 8; i++) ah[i] = pack_hi_lo(av[i].x, av[i].y, al[i]);
        if (ks < 7) load_A_raw<GUARD>(A, row0, (ks + 1) * 16, lane, av);
        mma_block(ah, al, bBase, (uint32_t)(ks * 32), acc);
    }
}

__device__ __forceinline__ void zero_acc(float acc[2][8][4]) {
#pragma unroll
    for (int mi = 0; mi < 2; mi++)
#pragma unroll
        for (int ni = 0; ni < 8; ni++)
#pragma unroll
            for (int j = 0; j < 4; j++) acc[mi][ni][j] = 0.f;
}

// Epilogue writer into fragment-quad layout. vals[ni] = pair of fp32 for this (row, ni).
__device__ __forceinline__ void store_frag_row(uint4* __restrict__ C, int row, int wn, int lane,
                                               const float2 vals[8])
{
    uint4* Cp = C + (size_t)row * 32 + (lane & 3);
#pragma unroll
    for (int ni2 = 0; ni2 < 8; ni2 += 2) {
        uint4 v;
        v.x = pack_hi_lo(vals[ni2].x,     vals[ni2].y,     v.z);
        v.y = pack_hi_lo(vals[ni2 + 1].x, vals[ni2 + 1].y, v.w);
        Cp[(size_t)(wn * 4 + (ni2 >> 1)) * 4] = v;
    }
}

// ---------------------------------------------------------------------------
// Weight prep: 33 fp32 [K=128][N=128] blocks -> single fp16 padded [n][k] images
// slots: 0 = W_embed; per layer l: 1+8l+{0..2}=Wm{s,r,e}, {3..5}=We{s,r,e}, {6,7}=Wh{a,b}
// ---------------------------------------------------------------------------
__global__ __launch_bounds__(256)
void prep_weights(const float* __restrict__ W_embed, const float* __restrict__ Wm,
                  const float* __restrict__ Wh, const float* __restrict__ We)
{
    int t = blockIdx.x;
    const float* src;
    if (t == 0) src = W_embed;
    else {
        int tt = t - 1, l = tt >> 3, j = tt & 7;
        if (j < 3)      src = Wm + (size_t)l * 384 * HID + j * 16384;
        else if (j < 6) src = We + (size_t)l * 384 * HID + (j - 3) * 16384;
        else            src = Wh + (size_t)l * 256 * HID + (j - 6) * 16384;
    }
    char* dst = (char*)(g_Bw + (size_t)t * 2176);
    for (int i = threadIdx.x; i < 16384; i += 256) {
        int k = i >> 7, n = i & 127;
        *(__half*)(dst + (uint32_t)(n * LDB + k * 2)) = __float2half_rn(src[i]);
    }
}

// ---------------------------------------------------------------------------
// Degree count + agg init: agg[r,:] = deg[r] * (P1[r,:] + bm)
// ---------------------------------------------------------------------------
__global__ __launch_bounds__(256)
void count_deg(const int* __restrict__ rec)
{
    int i = blockIdx.x * 256 + threadIdx.x;
    if (i < N_EDGES) atomicAdd(&g_deg[rec[i]], 1);
}
__global__ __launch_bounds__(256)
void agg_init(const float* __restrict__ P, const float* __restrict__ bm,
              float* __restrict__ agg)
{
    int idx = blockIdx.x * 256 + threadIdx.x;   // over N_PAD*128
    int r = idx >> 7, c = idx & 127;
    float d = (float)g_deg[r];
    agg[idx] = d * (P[(size_t)r * 512 + 128 + c] + bm[c]);
}

// ---------------------------------------------------------------------------
// proj_gemm: grid (4, GY). P[:, y*128:(y+1)*128] = h @ Wblock[y], m grid-stride
// ---------------------------------------------------------------------------
__global__ __launch_bounds__(GT, 2)
void proj_gemm(const uint4* __restrict__ A, int sbase, float* __restrict__ C)
{
    extern __shared__ char smem[];
    uint32_t sb = smem_u32(smem);
    const int tid = threadIdx.x, wid = tid >> 5, lane = tid & 31;
    const int y = blockIdx.x;
    const int wm = wid & 3, wn = wid >> 2;
    const int r4 = lane >> 2, c2 = (lane & 3) * 2;

    stage_B(sbase + ((y < 2) ? y : y + 1), tid, smem, 0);
    __syncthreads();

    for (int m0 = blockIdx.y * 128; m0 < N_PAD; m0 += gridDim.y * 128) {
        float acc[2][8][4];
        zero_acc(acc);
        mma_pass_bf(A, m0, sb, 0, wid, lane, acc);

#pragma unroll
        for (int mi = 0; mi < 2; mi++) {
#pragma unroll
            for (int jh = 0; jh < 2; jh++) {
                int row = m0 + wm * 32 + mi * 16 + jh * 8 + r4;
                float* Cp = C + (size_t)row * 512 + y * 128;
#pragma unroll
                for (int ni = 0; ni < 8; ni++) {
                    int col = wn * 64 + ni * 8 + c2;
                    *(float2*)(Cp + col) = make_float2(acc[mi][ni][jh * 2 + 0],
                                                       acc[mi][ni][jh * 2 + 1]);
                }
            }
        }
    }
}

// ---------------------------------------------------------------------------
// embed_gemm: C_frag = h_in(fp32, guarded) @ B0 + bias   (m grid-stride)
// ---------------------------------------------------------------------------
__global__ __launch_bounds__(GT, 2)
void embed_gemm(const float* __restrict__ A, int slot,
                const float* __restrict__ bias, uint4* __restrict__ C)
{
    extern __shared__ char smem[];
    uint32_t sb = smem_u32(smem);
    const int tid = threadIdx.x, wid = tid >> 5, lane = tid & 31;
    const int wm = wid & 3, wn = wid >> 2;
    const int r4 = lane >> 2, c2 = (lane & 3) * 2;

    stage_B(slot, tid, smem, 0);
    __syncthreads();

    for (int m0 = blockIdx.x * 128; m0 < N_PAD; m0 += gridDim.x * 128) {
        float acc[2][8][4];
        zero_acc(acc);
        mma_pass_f32<true>(A, m0, sb, 0, wid, lane, acc);

#pragma unroll
        for (int mi = 0; mi < 2; mi++) {
#pragma unroll
            for (int jh = 0; jh < 2; jh++) {
                int row = m0 + wm * 32 + mi * 16 + jh * 8 + r4;
                float2 vals[8];
#pragma unroll
                for (int ni = 0; ni < 8; ni++) {
                    int col = wn * 64 + ni * 8 + c2;
                    float2 b = *(const float2*)(bias + col);
                    vals[ni] = make_float2(acc[mi][ni][jh * 2 + 0] + b.x,
                                           acc[mi][ni][jh * 2 + 1] + b.y);
                }
                store_frag_row(C, row, wn, lane, vals);
            }
        }
    }
}

// ---------------------------------------------------------------------------
// hnew_gemm: C_frag = h_frag @ Wh_a + agg(fp32) @ Wh_b + bias. Both B images resident.
// ---------------------------------------------------------------------------
__global__ __launch_bounds__(GT, 2)
void hnew_gemm(const uint4* __restrict__ A1, int slot1,
               const float* __restrict__ A2, int slot2,
               const float* __restrict__ bias, uint4* __restrict__ C)
{
    extern __shared__ char smem[];
    uint32_t sb = smem_u32(smem);
    const int tid = threadIdx.x, wid = tid >> 5, lane = tid & 31;
    const int wm = wid & 3, wn = wid >> 2;
    const int r4 = lane >> 2, c2 = (lane & 3) * 2;

    stage_B(slot1, tid, smem, 0);
    stage_B(slot2, tid, smem, TILE_BYTES);
    __syncthreads();

    for (int m0 = blockIdx.x * 128; m0 < N_PAD; m0 += gridDim.x * 128) {
        float acc[2][8][4];
        zero_acc(acc);
        mma_pass_bf(A1, m0, sb, 0, wid, lane, acc);
        mma_pass_f32<false>(A2, m0, sb, TILE_BYTES, wid, lane, acc);

#pragma unroll
        for (int mi = 0; mi < 2; mi++) {
#pragma unroll
            for (int jh = 0; jh < 2; jh++) {
                int row = m0 + wm * 32 + mi * 16 + jh * 8 + r4;
                float2 vals[8];
#pragma unroll
                for (int ni = 0; ni < 8; ni++) {
                    int col = wn * 64 + ni * 8 + c2;
                    float2 b = *(const float2*)(bias + col);
                    vals[ni] = make_float2(acc[mi][ni][jh * 2 + 0] + b.x,
                                           acc[mi][ni][jh * 2 + 1] + b.y);
                }
                store_frag_row(C, row, wn, lane, vals);
            }
        }
    }
}

// ---------------------------------------------------------------------------
// edge_gemm: grid (2, GY), m grid-stride
//  x==0: red.add agg[r] += e@Wm_e + P0[s]          (bm and P1[r] folded into agg_init)
//  x==1: e' = e@We_e + be + P2[s] + P3[r] -> e_out (fragment layout)
// ---------------------------------------------------------------------------
__global__ __launch_bounds__(GT, 2)
void edge_gemm(const uint4* __restrict__ E_in, int slot_m, int slot_e,
               const float* __restrict__ be,
               const float* __restrict__ P,
               const int* __restrict__ send, const int* __restrict__ rec,
               float* __restrict__ agg, uint4* __restrict__ e_out)
{
    extern __shared__ char smem[];
    uint32_t sb = smem_u32(smem);
    const int tid = threadIdx.x, wid = tid >> 5, lane = tid & 31;
    const int which = blockIdx.x;
    const int wm = wid & 3, wn = wid >> 2;
    const int r4 = lane >> 2, c2 = (lane & 3) * 2;

    stage_B(which ? slot_e : slot_m, tid, smem, 0);
    __syncthreads();

    for (int m0 = blockIdx.y * 128; m0 < N_EDGES; m0 += gridDim.y * 128) {
        float acc[2][8][4];
        zero_acc(acc);
        mma_pass_bf(E_in, m0, sb, 0, wid, lane, acc);

        if (which == 0) {
#pragma unroll
            for (int mi = 0; mi < 2; mi++) {
#pragma unroll
                for (int jh = 0; jh < 2; jh++) {
                    int row = m0 + wm * 32 + mi * 16 + jh * 8 + r4;
                    int s = send[row], r = rec[row];
                    const float* Ps = P + (size_t)s * 512;
                    float* ap = agg + (size_t)r * HID;
#pragma unroll
                    for (int ni = 0; ni < 8; ni++) {
                        int col = wn * 64 + ni * 8 + c2;
                        float2 p = *(const float2*)(Ps + col);
                        red_add_v2(ap + col,
                                   acc[mi][ni][jh * 2 + 0] + p.x,
                                   acc[mi][ni][jh * 2 + 1] + p.y);
                    }
                }
            }
        } else {
#pragma unroll
            for (int mi = 0; mi < 2; mi++) {
#pragma unroll
                for (int jh = 0; jh < 2; jh++) {
                    int row = m0 + wm * 32 + mi * 16 + jh * 8 + r4;
                    int s = send[row], r = rec[row];
                    const float* Ps = P + (size_t)s * 512 + 256;
                    const float* Pr = P + (size_t)r * 512 + 384;
                    float2 vals[8];
#pragma unroll
                    for (int ni = 0; ni < 8; ni++) {
                        int col = wn * 64 + ni * 8 + c2;
                        float2 b = *(const float2*)(be + col);
                        float2 p = *(const float2*)(Ps + col);
                        float2 q = *(const float2*)(Pr + col);
                        vals[ni] = make_float2(acc[mi][ni][jh * 2 + 0] + b.x + p.x + q.x,
                                               acc[mi][ni][jh * 2 + 1] + b.y + p.y + q.y);
                    }
                    store_frag_row(e_out, row, wn, lane, vals);
                }
            }
        }
    }
}

// ---------------------------------------------------------------------------
// Edge embedding: e0_frag = E[:,0:16] @ W[16,128] + b
// 128 threads = 4 edges x 32 quad-slots per iter
// ---------------------------------------------------------------------------
__global__ __launch_bounds__(128)
void embed_e_kernel(const float* __restrict__ e_in, const float* __restrict__ W,
                    const float* __restrict__ b, uint4* __restrict__ out)
{
    __shared__ float Ws[16 * 128];
    __shared__ float bs[128];
    for (int i = threadIdx.x; i < 16 * 128; i += blockDim.x) Ws[i] = W[i];
    if (threadIdx.x < 128) bs[threadIdx.x] = b[threadIdx.x];
    __syncthreads();
    const int sub = threadIdx.x >> 5;       // 0..3: edge within group
    const int u = threadIdx.x & 31;         // quad slot: ks = u>>2, i = u&3
    const int ks = u >> 2, ii = u & 3;
    const int cA = (ks * 8 + ii) * 2;       // first col of pair A
    const int cB = cA + 8;                  // partner pair (cp+4)
    for (int k = blockIdx.x * 4 + sub; k < N_EDGES; k += gridDim.x * 4) {
        const float* er = e_in + (size_t)k * 16;
        float a0 = bs[cA], a1 = bs[cA + 1], b0 = bs[cB], b1 = bs[cB + 1];
#pragma unroll
        for (int j = 0; j < 16; j++) {
            float e = er[j];
            a0 += e * Ws[j * 128 + cA];
            a1 += e * Ws[j * 128 + cA + 1];
            b0 += e * Ws[j * 128 + cB];
            b1 += e * Ws[j * 128 + cB + 1];
        }
        uint4 v;
        v.x = pack_hi_lo(a0, a1, v.z);
        v.y = pack_hi_lo(b0, b1, v.w);
        out[(size_t)k * 32 + u] = v;
    }
}

// ---------------------------------------------------------------------------
// Global add-pool from fragment layout: val = hi + lo
// ---------------------------------------------------------------------------
__global__ __launch_bounds__(128)
void pool_kernel(const uint4* __restrict__ h, const int* __restrict__ batch,
                 float* __restrict__ out)
{
    const int n = blockIdx.x;
    const int c = threadIdx.x;
    const int g = batch[n];
    int cp = c >> 1;
    uint4 v = h[(size_t)n * 32 + (cp >> 3) * 4 + (cp & 3)];
    int pos = (cp >> 2) & 1;
    uint32_t uh = pos ? v.y : v.x;
    uint32_t ul = pos ? v.w : v.z;
    uint32_t sh = (c & 1) ? 16 : 0;
    float hi = __half2float(__ushort_as_half((unsigned short)((uh >> sh) & 0xFFFF)));
    float lo = __half2float(__ushort_as_half((unsigned short)((ul >> sh) & 0xFFFF)));
    atomicAdd(&out[(size_t)g * HID + c], hi + lo);
}

// ---------------------------------------------------------------------------
// Launch
// ---------------------------------------------------------------------------
extern "C" void kernel_launch(void* const* d_in, const int* in_sizes, int n_in,
                              void* d_out, int out_size)
{
    const float* h_in     = (const float*)d_in[0];
    const float* e_in     = (const float*)d_in[1];
    const int*   edge_idx = (const int*)  d_in[2];
    const int*   batch    = (const int*)  d_in[3];
    const float* W_embed  = (const float*)d_in[4];
    const float* b_embed  = (const float*)d_in[5];
    const float* W_eembed = (const float*)d_in[6];
    const float* b_eembed = (const float*)d_in[7];
    const float* Wm       = (const float*)d_in[8];
    const float* bm       = (const float*)d_in[9];
    const float* Wh       = (const float*)d_in[10];
    const float* bh       = (const float*)d_in[11];
    const float* We       = (const float*)d_in[12];
    const float* be       = (const float*)d_in[13];
    float*       out      = (float*)d_out;

    cudaFuncSetAttribute(proj_gemm,  cudaFuncAttributeMaxDynamicSharedMemorySize, SMEM_1);
    cudaFuncSetAttribute(embed_gemm, cudaFuncAttributeMaxDynamicSharedMemorySize, SMEM_1);
    cudaFuncSetAttribute(hnew_gemm,  cudaFuncAttributeMaxDynamicSharedMemorySize, SMEM_2);
    cudaFuncSetAttribute(edge_gemm,  cudaFuncAttributeMaxDynamicSharedMemorySize, SMEM_1);

    uint4 *hbuf, *ebuf;
    float *Pp, *aggp;
    int* degp;
    cudaGetSymbolAddress((void**)&hbuf, g_hbf);
    cudaGetSymbolAddress((void**)&ebuf, g_ebf);
    cudaGetSymbolAddress((void**)&Pp,   g_P);
    cudaGetSymbolAddress((void**)&aggp, g_agg);
    cudaGetSymbolAddress((void**)&degp, g_deg);

    uint4* hb[2] = { hbuf, hbuf + (size_t)N_PAD * 32 };
    uint4* eb[2] = { ebuf, ebuf + (size_t)N_EDGES * 32 };
    const int* send = edge_idx;
    const int* rec  = edge_idx + N_EDGES;

    // Degree (once per launch) + weight prep + embeddings
    cudaMemsetAsync(degp, 0, N_PAD * sizeof(int));
    count_deg<<<(N_EDGES + 255) / 256, 256>>>(rec);
    prep_weights<<<33, 256>>>(W_embed, Wm, Wh, We);
    embed_e_kernel<<<2048, 128>>>(e_in, W_eembed, b_eembed, eb[0]);
    embed_gemm<<<296, GT, SMEM_1>>>(h_in, 0, b_embed, hb[0]);

    int cur = 0;
    for (int l = 0; l < N_LAYERS; l++) {
        int sbase = 1 + l * 8;
        const float* bm_l = bm + (size_t)l * HID;
        const float* bh_l = bh + (size_t)l * HID;
        const float* be_l = be + (size_t)l * HID;
        uint4* hcur = hb[cur];
        uint4* ecur = eb[cur];
        uint4* hnxt = hb[1 - cur];
        uint4* enxt = eb[1 - cur];

        // P = h @ [Wm_s | Wm_r | We_s | We_r]  -> [N, 512] fp32
        proj_gemm<<<dim3(4, 148), GT, SMEM_1>>>(hcur, sbase, Pp);

        // agg = deg * (P1 + bm)   (replaces memset; folds bm + P1[rec] terms)
        agg_init<<<(N_PAD * 128) / 256, 256>>>(Pp, bm_l, aggp);

        // Fused edge GEMMs: x=0 message+scatter, x=1 edge update (B staged once/CTA)
        edge_gemm<<<dim3(2, 592), GT, SMEM_1>>>(
            ecur, sbase + 2, sbase + 5, be_l, Pp, send, rec, aggp, enxt);

        // h_new = [h | agg] @ Wh + bh
        hnew_gemm<<<296, GT, SMEM_2>>>(hcur, sbase + 6, aggp, sbase + 7, bh_l, hnxt);

        cur = 1 - cur;
    }

    cudaMemsetAsync(d_out, 0, (size_t)NUM_GRAPHS * HID * sizeof(float));
    pool_kernel<<<N_NODES, 128>>>(hb[cur], batch, out);
}